// round 13
// baseline (speedup 1.0000x reference)
#include <cuda_runtime.h>
#include <cuda_fp16.h>
#include <cstdint>
#include <cstring>
#include <dlfcn.h>

#define BATCH 8192
#define INF   4096
#define OUTF  4096
#define BS    64
#define NBR   64
#define BPR   16

// ================= shared scratch (allocation-free) =================
__device__ __half g_xh[(size_t)BATCH * INF];          // 64MB
__device__ __half g_wt[(size_t)NBR * BPR * BS * BS];  // 8MB
__device__ int    g_ops[16 * 64];                     // per-group schedule: c<<16|rl<<8|j

__host__ __device__ __forceinline__ uint32_t sw128(uint32_t b) {
    return b ^ ((b >> 3) & 0x70);
}

// ================= prepasses: SW128-swizzled tiles =================
// x tile (mt,c): 256 rows x 64 fp16 (128B rows) at offset (mt*64+c)*32768
__global__ void conv_x_tiled(const float* __restrict__ x) {
    size_t i = ((size_t)blockIdx.x * 256 + threadIdx.x) * 8;
    int row = (int)(i >> 12), col = (int)(i & 4095);
    float4 a = *(const float4*)(x + i);
    float4 b = *(const float4*)(x + i + 4);
    __half2 h0 = __floats2half2_rn(a.x, a.y), h1 = __floats2half2_rn(a.z, a.w);
    __half2 h2 = __floats2half2_rn(b.x, b.y), h3 = __floats2half2_rn(b.z, b.w);
    uint4 o; o.x = *(uint32_t*)&h0; o.y = *(uint32_t*)&h1; o.z = *(uint32_t*)&h2; o.w = *(uint32_t*)&h3;
    int mt = row >> 8, rl = row & 255, c = col >> 6, k = col & 63;
    size_t off = ((size_t)(mt * 64 + c) << 15) + sw128((uint32_t)(rl * 128 + k * 2));
    *(uint4*)((char*)g_xh + off) = o;
}
// W block blk=(r*16+j): 64 o-rows x 64 b fp16 at blk*8192 (B operand [N][K])
__global__ void conv_w_tiled(const float* __restrict__ v) {
    size_t i = ((size_t)blockIdx.x * 256 + threadIdx.x) * 8;
    int blk = (int)(i >> 12), w = (int)(i & 4095);
    int o = w >> 6, b = w & 63;
    float4 a = *(const float4*)(v + i);
    float4 bb = *(const float4*)(v + i + 4);
    __half2 h0 = __floats2half2_rn(a.x, a.y), h1 = __floats2half2_rn(a.z, a.w);
    __half2 h2 = __floats2half2_rn(bb.x, bb.y), h3 = __floats2half2_rn(bb.z, bb.w);
    uint4 o4; o4.x = *(uint32_t*)&h0; o4.y = *(uint32_t*)&h1; o4.z = *(uint32_t*)&h2; o4.w = *(uint32_t*)&h3;
    size_t off = ((size_t)blk << 13) + sw128((uint32_t)(o * 128 + b * 2));
    *(uint4*)((char*)g_wt + off) = o4;
}
// schedule: for each group g (4 row-blocks), ops sorted by column index
__global__ void build_sched(const int* __restrict__ cols) {
    int g = threadIdx.x;
    if (g >= 16) return;
    int n = 0;
    for (int c = 0; c < 64; c++)
        for (int rl = 0; rl < 4; rl++)
            for (int j = 0; j < 16; j++)
                if (cols[(g * 4 + rl) * 16 + j] == c)
                    g_ops[g * 64 + n++] = (c << 16) | (rl << 8) | j;
}

// ================= tcgen05 kernel source (NVRTC, sm_103a) =================
// Group of 4 row-blocks per CTA; x tiles loaded ONCE per group.
// smem: x-ring 4x32KB @0, W-ring 8x8KB @131072, barriers @196608 (25), tmemptr @196808
static const char* kSRC = R"XX(
typedef unsigned long long ull;
#define WAITB(ad,ph) {unsigned _d; do{ asm volatile("{.reg .pred P; mbarrier.try_wait.parity.acquire.cta.shared::cta.b64 P,[%1],%2; selp.b32 %0,1,0,P;}":"=r"(_d):"r"(ad),"r"(ph):"memory"); }while(!_d);}
#define MMA(d,ad,bd,e) asm volatile("{.reg .pred p; setp.ne.u32 p,%4,0; tcgen05.mma.cta_group::1.kind::f16 [%0],%1,%2,%3,{%5,%5,%5,%5},p;}"::"r"(d),"l"(ad),"l"(bd),"r"(0x8100010u),"r"(e),"r"(0u):"memory")
#define CPB(d,s,n,b) asm volatile("cp.async.bulk.shared::cluster.global.mbarrier::complete_tx::bytes [%0],[%1],%2,[%3];"::"r"(d),"l"(s),"r"(n),"r"(b):"memory")
#define EXPN(a,n) asm volatile("mbarrier.arrive.expect_tx.shared.b64 _,[%0],%1;"::"r"(a),"r"(n):"memory")
#define CMT(a) asm volatile("tcgen05.commit.cta_group::1.mbarrier::arrive::one.shared::cluster.b64 [%0];"::"r"(a):"memory")
#define LDT(rg,ad) asm volatile("tcgen05.ld.sync.aligned.32x32b.x32.b32 {%0,%1,%2,%3,%4,%5,%6,%7,%8,%9,%10,%11,%12,%13,%14,%15,%16,%17,%18,%19,%20,%21,%22,%23,%24,%25,%26,%27,%28,%29,%30,%31},[%32];":"=r"(rg[0]),"=r"(rg[1]),"=r"(rg[2]),"=r"(rg[3]),"=r"(rg[4]),"=r"(rg[5]),"=r"(rg[6]),"=r"(rg[7]),"=r"(rg[8]),"=r"(rg[9]),"=r"(rg[10]),"=r"(rg[11]),"=r"(rg[12]),"=r"(rg[13]),"=r"(rg[14]),"=r"(rg[15]),"=r"(rg[16]),"=r"(rg[17]),"=r"(rg[18]),"=r"(rg[19]),"=r"(rg[20]),"=r"(rg[21]),"=r"(rg[22]),"=r"(rg[23]),"=r"(rg[24]),"=r"(rg[25]),"=r"(rg[26]),"=r"(rg[27]),"=r"(rg[28]),"=r"(rg[29]),"=r"(rg[30]),"=r"(rg[31]):"r"(ad))
struct __align__(16) F4 { float x,y,z,w; };
extern "C" __global__ void __launch_bounds__(256,1) bsr_tc(
    const unsigned short* xh, const unsigned short* wt, const int* gops,
    const float* bias, float* out)
{
    extern __shared__ char smbuf[];
    unsigned sb; asm("{.reg .u64 t; cvta.to.shared.u64 t,%1; cvt.u32.u64 %0,t;}":"=r"(sb):"l"(smbuf));
    const int tid = threadIdx.x, wid = tid >> 5, lid = tid & 31;
    const int g = blockIdx.x, mt = blockIdx.y;
    const unsigned B = sb + 196608;
    if (tid == 0)
        for (int i = 0; i < 25; i++)
            asm volatile("mbarrier.init.shared.b64 [%0],1;"::"r"(B+8*i):"memory");
    if (wid == 0) {
        asm volatile("tcgen05.alloc.cta_group::1.sync.aligned.shared::cta.b32 [%0],512;"::"r"(B+200):"memory");
        asm volatile("tcgen05.relinquish_alloc_permit.cta_group::1.sync.aligned;");
    }
    __syncthreads();
    unsigned tmem; asm volatile("ld.shared.b32 %0,[%1];":"=r"(tmem):"r"(B+200));
    if (tid == 0) {
        const char* xg = (const char*)xh + ((ull)mt << 21);
        const char* wg = (const char*)wt + ((ull)g << 19);
        int ops[64];
        for (int i = 0; i < 64; i++) ops[i] = gops[g*64 + i];
        int tl[64]; int ntl = 0; int pc = -1;
        for (int i = 0; i < 64; i++) { int c = ops[i] >> 16; if (c != pc) { tl[ntl++] = c; pc = c; } }
        const unsigned xf = B, xd = B+32, wf = B+64, wd = B+128, ald = B+192;
        for (int t = 0; t < 4; t++) {
            EXPN(xf+8*t, 32768u);
            CPB(sb + 32768u*t, xg + (ull)tl[t]*32768ULL, 32768u, xf+8*t);
        }
        for (int i = 0; i < 8; i++) {
            int rl = (ops[i] >> 8) & 255, j = ops[i] & 255;
            EXPN(wf+8*i, 8192u);
            CPB(sb + 131072u + 8192u*i, wg + (ull)(rl*16 + j)*8192ULL, 8192u, wf+8*i);
        }
        int xi = -1; pc = -1; unsigned fm = 0xFu;
        ull ax = 0;
        for (int i = 0; i < 64; i++) {
            int c = ops[i] >> 16, rl = (ops[i] >> 8) & 255;
            if (c != pc) {
                if (xi >= 0) CMT(xd + 8*(xi & 3));
                pc = c; xi++;
                int tn = xi + 3;
                if (tn >= 4 && tn < ntl) {
                    WAITB(xd + 8*(tn & 3), (unsigned)(((tn >> 2) - 1) & 1));
                    EXPN(xf + 8*(tn & 3), 32768u);
                    CPB(sb + 32768u*(tn & 3), xg + (ull)tl[tn]*32768ULL, 32768u, xf + 8*(tn & 3));
                }
                WAITB(xf + 8*(xi & 3), (unsigned)((xi >> 2) & 1));
                ax = 0x4000404000010000ULL | (((sb + 32768u*(xi & 3)) >> 4) & 0x3FFF);
            }
            int s = i & 7;
            WAITB(wf + 8*s, (unsigned)((i >> 3) & 1));
            ull aw = 0x4000404000010000ULL | (((sb + 131072u + 8192u*s) >> 4) & 0x3FFF);
            unsigned e0 = ((fm >> rl) & 1u) ? 0u : 1u;
            fm &= ~(1u << rl);
            unsigned dc = tmem + rl*128;
            for (int k = 0; k < 4; k++) {
                MMA(dc,      ax + 2*k,        aw + 2*k, k ? 1u : e0);
                MMA(dc + 64, ax + 1024 + 2*k, aw + 2*k, k ? 1u : e0);
            }
            CMT(wd + 8*s);
            if (i + 8 < 64) {
                int o2 = ops[i + 8];
                int rl2 = (o2 >> 8) & 255, j2 = o2 & 255;
                WAITB(wd + 8*s, (unsigned)((i >> 3) & 1));
                EXPN(wf + 8*s, 8192u);
                CPB(sb + 131072u + 8192u*s, wg + (ull)(rl2*16 + j2)*8192ULL, 8192u, wf + 8*s);
            }
        }
        CMT(ald);
        WAITB(ald, 0u);
    }
    __syncthreads();
    asm volatile("tcgen05.fence::after_thread_sync;":::"memory");
    int half = wid >> 2, lg = wid & 3;
    int row = mt*256 + half*128 + lg*32 + lid;
    float* po = out + (ull)row*4096 + g*256;
    const float* pb = bias + g*256;
    for (int ch = 0; ch < 8; ch++) {
        int rl = ch >> 1, co = (ch & 1)*32;
        unsigned rg[32];
        LDT(rg, tmem + rl*128 + half*64 + co);
        asm volatile("tcgen05.wait::ld.sync.aligned;":::"memory");
        int cb = rl*64 + co;
        for (int q = 0; q < 32; q += 4) {
            F4 b4 = *(const F4*)(pb + cb + q);
            F4 v;
            v.x = *(float*)&rg[q]   + b4.x; v.y = *(float*)&rg[q+1] + b4.y;
            v.z = *(float*)&rg[q+2] + b4.z; v.w = *(float*)&rg[q+3] + b4.w;
            *(F4*)(po + cb + q) = v;
        }
    }
    __syncthreads();
    if (wid == 0)
        asm volatile("tcgen05.dealloc.cta_group::1.sync.aligned.b32 %0,512;"::"r"(tmem):"memory");
}
)XX";

// ================= NVRTC + driver glue (global ctor = pre-checkpoint) =================
struct Jit {
    bool ok = false;
    void* fn = nullptr;
    void* ctx = nullptr;
    void* xp = nullptr;
    void* wp = nullptr;
    void* opsp = nullptr;
    cudaStream_t s2 = nullptr;
    cudaEvent_t evA = nullptr, evB = nullptr;
    int (*Launch)(void*,unsigned,unsigned,unsigned,unsigned,unsigned,unsigned,unsigned,void*,void**,void**) = nullptr;
    int (*CtxSet)(void*) = nullptr;
    Jit() {
        void* hn = dlopen("libnvrtc.so.13", RTLD_NOW);
        if (!hn) hn = dlopen("libnvrtc.so.12", RTLD_NOW);
        if (!hn) hn = dlopen("libnvrtc.so", RTLD_NOW);
        void* hc = dlopen("libcuda.so.1", RTLD_NOW);
        if (!hn || !hc) return;
        auto create  = (int(*)(void**,const char*,const char*,int,const char* const*,const char* const*))dlsym(hn,"nvrtcCreateProgram");
        auto compile = (int(*)(void*,int,const char* const*))dlsym(hn,"nvrtcCompileProgram");
        auto cbsz    = (int(*)(void*,size_t*))dlsym(hn,"nvrtcGetCUBINSize");
        auto cbin    = (int(*)(void*,char*))dlsym(hn,"nvrtcGetCUBIN");
        auto ptxsz   = (int(*)(void*,size_t*))dlsym(hn,"nvrtcGetPTXSize");
        auto ptx     = (int(*)(void*,char*))dlsym(hn,"nvrtcGetPTX");
        auto cuInit_ = (int(*)(unsigned))dlsym(hc,"cuInit");
        auto devGet  = (int(*)(int*,int))dlsym(hc,"cuDeviceGet");
        auto ctxRet  = (int(*)(void**,int))dlsym(hc,"cuDevicePrimaryCtxRetain");
        auto modLoad = (int(*)(void**,const void*))dlsym(hc,"cuModuleLoadData");
        auto modFn   = (int(*)(void**,void*,const char*))dlsym(hc,"cuModuleGetFunction");
        auto fnAttr  = (int(*)(void*,int,int))dlsym(hc,"cuFuncSetAttribute");
        CtxSet = (int(*)(void*))dlsym(hc,"cuCtxSetCurrent");
        Launch = (int(*)(void*,unsigned,unsigned,unsigned,unsigned,unsigned,unsigned,unsigned,void*,void**,void**))dlsym(hc,"cuLaunchKernel");
        if (!create || !compile || !cbsz || !cbin || !ptxsz || !ptx || !cuInit_ || !devGet ||
            !ctxRet || !CtxSet || !modLoad || !modFn || !fnAttr || !Launch) return;

        if (cudaGetSymbolAddress(&xp, g_xh) != cudaSuccess) return;
        if (cudaGetSymbolAddress(&wp, g_wt) != cudaSuccess) return;
        if (cudaGetSymbolAddress(&opsp, g_ops) != cudaSuccess) return;
        if (cudaStreamCreateWithFlags(&s2, cudaStreamNonBlocking) != cudaSuccess) return;
        if (cudaEventCreateWithFlags(&evA, cudaEventDisableTiming) != cudaSuccess) return;
        if (cudaEventCreateWithFlags(&evB, cudaEventDisableTiming) != cudaSuccess) return;

        if (cuInit_(0)) return;
        int dev; if (devGet(&dev, 0)) return;
        if (ctxRet(&ctx, dev)) return;
        if (CtxSet(ctx)) return;
        void* prog;
        if (create(&prog, kSRC, "bsr_tc.cu", 0, nullptr, nullptr)) return;
        const char* opts[] = {"--gpu-architecture=sm_103a"};
        if (compile(prog, 1, opts)) return;
        void* mod = nullptr;
        size_t n = 0;
        if (cbsz(prog, &n) == 0 && n > 0) {
            char* buf = new char[n];
            if (cbin(prog, buf) == 0 && modLoad(&mod, buf) != 0) mod = nullptr;
        }
        if (!mod) {
            if (ptxsz(prog, &n) || n == 0) return;
            char* buf = new char[n];
            if (ptx(prog, buf)) return;
            if (modLoad(&mod, buf)) return;
        }
        if (modFn(&fn, mod, "bsr_tc")) return;
        if (fnAttr(fn, 8 /*MAX_DYNAMIC_SHARED_SIZE_BYTES*/, 196864)) return;
        ok = true;
    }
};
static Jit g_jit;

// ================= mma.sync fallback (proven ~242us) =================
__global__ void conv_x_flat(const float* __restrict__ x) {
    size_t i = ((size_t)blockIdx.x * 256 + threadIdx.x) * 8;
    float4 a = *(const float4*)(x + i);
    float4 b = *(const float4*)(x + i + 4);
    __half2 h0 = __floats2half2_rn(a.x, a.y), h1 = __floats2half2_rn(a.z, a.w);
    __half2 h2 = __floats2half2_rn(b.x, b.y), h3 = __floats2half2_rn(b.z, b.w);
    uint4 o; o.x = *(uint32_t*)&h0; o.y = *(uint32_t*)&h1; o.z = *(uint32_t*)&h2; o.w = *(uint32_t*)&h3;
    *(uint4*)(g_xh + i) = o;
}
__global__ void conv_w_flat(const float* __restrict__ v) {
    __shared__ float t[64][65];
    int blk = blockIdx.x, tid = threadIdx.x;
    const float* src = v + (size_t)blk * 4096;
    #pragma unroll
    for (int k = 0; k < 16; k++) t[k * 4 + (tid >> 6)][tid & 63] = src[(k * 4 + (tid >> 6)) * 64 + (tid & 63)];
    __syncthreads();
    __half* dst = g_wt + (size_t)blk * 4096;
    #pragma unroll
    for (int k = 0; k < 16; k++) {
        int b = k * 4 + (tid >> 6), o = tid & 63;
        dst[b * 64 + o] = __float2half(t[o][b]);
    }
}
__device__ __forceinline__ uint32_t smem_u32(const void* p) {
    uint32_t a;
    asm("{ .reg .u64 t; cvta.to.shared.u64 t, %1; cvt.u32.u64 %0, t; }" : "=r"(a) : "l"(p));
    return a;
}
__device__ __forceinline__ void cp16(uint32_t s, const void* g) {
    asm volatile("cp.async.cg.shared.global [%0], [%1], 16;" :: "r"(s), "l"(g));
}
__device__ __forceinline__ void ldsm4(uint32_t* d, uint32_t a) {
    asm volatile("ldmatrix.sync.aligned.m8n8.x4.shared.b16 {%0,%1,%2,%3}, [%4];"
                 : "=r"(d[0]), "=r"(d[1]), "=r"(d[2]), "=r"(d[3]) : "r"(a));
}
__device__ __forceinline__ void ldsm4t(uint32_t* d, uint32_t a) {
    asm volatile("ldmatrix.sync.aligned.m8n8.x4.trans.shared.b16 {%0,%1,%2,%3}, [%4];"
                 : "=r"(d[0]), "=r"(d[1]), "=r"(d[2]), "=r"(d[3]) : "r"(a));
}
__device__ __forceinline__ void mma16816(float* c, const uint32_t* a, const uint32_t* b) {
    asm volatile(
        "mma.sync.aligned.m16n8k16.row.col.f32.f16.f16.f32 "
        "{%0,%1,%2,%3}, {%4,%5,%6,%7}, {%8,%9}, {%0,%1,%2,%3};"
        : "+f"(c[0]), "+f"(c[1]), "+f"(c[2]), "+f"(c[3])
        : "r"(a[0]), "r"(a[1]), "r"(a[2]), "r"(a[3]), "r"(b[0]), "r"(b[1]));
}
#define FB_SMEM 163840
__global__ void __launch_bounds__(256, 1)
bsr_fb(const float* __restrict__ bias, const int* __restrict__ cols, float* __restrict__ out) {
    extern __shared__ char smem[];
    const uint32_t sb = smem_u32(smem);
    const int r = blockIdx.x, mt = blockIdx.y;
    const int tid = threadIdx.x, warp = tid >> 5, lane = tid & 31;
    const int wm = warp >> 1, wn = warp & 1;
    int cidx[BPR];
    #pragma unroll
    for (int j = 0; j < BPR; j++) cidx[j] = __ldg(&cols[r * BPR + j]);
    const __half* xg = g_xh + (size_t)mt * 256 * INF;
    const __half* wg = g_wt + (size_t)r * BPR * BS * BS;
    float acc[4][4][4];
    #pragma unroll
    for (int mi = 0; mi < 4; mi++)
        #pragma unroll
        for (int ni = 0; ni < 4; ni++)
            #pragma unroll
            for (int q = 0; q < 4; q++) acc[mi][ni][q] = 0.0f;
    auto issue = [&](int j) {
        int s = j & 3;
        const char* xsrc = (const char*)(xg + (size_t)cidx[j] * BS);
        uint32_t xs = sb + s * 32768;
        #pragma unroll
        for (int k = 0; k < 8; k++) {
            int q = tid + k * 256, row = q >> 3, ch = q & 7;
            cp16(xs + row * 128 + ((ch ^ (row & 7)) << 4), xsrc + (size_t)row * (INF * 2) + ch * 16);
        }
        const char* wsrc = (const char*)(wg + (size_t)j * BS * BS);
        uint32_t ws = sb + 131072 + s * 8192;
        #pragma unroll
        for (int k = 0; k < 2; k++) {
            int q = tid + k * 256, row = q >> 3, ch = q & 7;
            cp16(ws + row * 128 + ((ch ^ (row & 7)) << 4), wsrc + row * 128 + ch * 16);
        }
        asm volatile("cp.async.commit_group;");
    };
    issue(0); issue(1); issue(2);
    const int mat = lane >> 3, rl = lane & 7;
    for (int j = 0; j < BPR; j++) {
        int rem = (BPR - 1) - j;
        if (rem >= 2)      asm volatile("cp.async.wait_group 2;");
        else if (rem == 1) asm volatile("cp.async.wait_group 1;");
        else               asm volatile("cp.async.wait_group 0;");
        __syncthreads();
        uint32_t xs = sb + (j & 3) * 32768;
        uint32_t ws = sb + 131072 + (j & 3) * 8192;
        #pragma unroll
        for (int ks = 0; ks < 4; ks++) {
            uint32_t a[4][4], b[4][2];
            #pragma unroll
            for (int mi = 0; mi < 4; mi++) {
                int row = wm * 64 + mi * 16 + (mat & 1) * 8 + rl;
                int ch = 2 * ks + (mat >> 1);
                ldsm4(a[mi], xs + row * 128 + ((ch ^ (row & 7)) << 4));
            }
            #pragma unroll
            for (int nh = 0; nh < 2; nh++) {
                int krow = ks * 16 + (mat & 1) * 8 + rl;
                int nch = wn * 4 + nh * 2 + (mat >> 1);
                uint32_t t[4];
                ldsm4t(t, ws + krow * 128 + ((nch ^ (krow & 7)) << 4));
                b[nh * 2][0] = t[0]; b[nh * 2][1] = t[1];
                b[nh * 2 + 1][0] = t[2]; b[nh * 2 + 1][1] = t[3];
            }
            #pragma unroll
            for (int mi = 0; mi < 4; mi++)
                #pragma unroll
                for (int ni = 0; ni < 4; ni++)
                    mma16816(acc[mi][ni], a[mi], b[ni]);
        }
        if (j + 3 < BPR) issue(j + 3);
    }
    #pragma unroll
    for (int mi = 0; mi < 4; mi++)
        #pragma unroll
        for (int ni = 0; ni < 4; ni++) {
            int rr = mt * 256 + wm * 64 + mi * 16 + (lane >> 2);
            int cc = r * BS + wn * 32 + ni * 8 + 2 * (lane & 3);
            float2 bv = *(const float2*)(bias + cc);
            float2 v0 = {acc[mi][ni][0] + bv.x, acc[mi][ni][1] + bv.y};
            float2 v1 = {acc[mi][ni][2] + bv.x, acc[mi][ni][3] + bv.y};
            *(float2*)(out + (size_t)rr * OUTF + cc) = v0;
            *(float2*)(out + (size_t)(rr + 8) * OUTF + cc) = v1;
        }
}

// ================= launch =================
extern "C" void kernel_launch(void* const* d_in, const int* in_sizes, int n_in,
                              void* d_out, int out_size) {
    const float* x      = (const float*)d_in[0];
    const float* values = (const float*)d_in[1];
    const float* bias   = (const float*)d_in[2];
    const int*   cols   = (const int*)d_in[3];
    float* out = (float*)d_out;

    if (g_jit.ok) {
        conv_x_tiled<<<16384, 256>>>(x);
        conv_w_tiled<<<2048, 256>>>(values);
        build_sched<<<1, 16>>>(cols);
        cudaEventRecord(g_jit.evA, 0);
        cudaStreamWaitEvent(g_jit.s2, g_jit.evA, 0);
        g_jit.CtxSet(g_jit.ctx);
        void* args[] = {&g_jit.xp, &g_jit.wp, &g_jit.opsp, (void*)&bias, (void*)&out};
        g_jit.Launch(g_jit.fn, 16, 32, 1, 256, 1, 1, 196864, (void*)g_jit.s2, args, nullptr);
        cudaEventRecord(g_jit.evB, g_jit.s2);
        cudaStreamWaitEvent(0, g_jit.evB, 0);
    } else {
        conv_x_flat<<<(BATCH * (size_t)INF / 8) / 256, 256>>>(x);
        conv_w_flat<<<NBR * BPR, 256>>>(values);
        cudaFuncSetAttribute(bsr_fb, cudaFuncAttributeMaxDynamicSharedMemorySize, FB_SMEM);
        bsr_fb<<<dim3(NBR, 32), 256, FB_SMEM>>>(bias, cols, out);
    }
}

// round 14
// speedup vs baseline: 1.1833x; 1.1833x over previous
#include <cuda_runtime.h>
#include <cuda_fp16.h>
#include <cstdint>
#include <cstring>
#include <dlfcn.h>

#define BATCH 8192
#define INF   4096
#define OUTF  4096
#define BS    64
#define NBR   64
#define BPR   16

// ================= shared scratch (allocation-free) =================
__device__ __half g_xh[(size_t)BATCH * INF];          // 64MB
__device__ __half g_wt[(size_t)NBR * BPR * BS * BS];  // 8MB
__device__ int    g_ops[16 * 64];                     // per-group schedule: c<<16|rl<<8|j

__host__ __device__ __forceinline__ uint32_t sw128(uint32_t b) {
    return b ^ ((b >> 3) & 0x70);
}

// ================= prepasses: SW128-swizzled tiles =================
__global__ void conv_x_tiled(const float* __restrict__ x) {
    size_t i = ((size_t)blockIdx.x * 256 + threadIdx.x) * 8;
    int row = (int)(i >> 12), col = (int)(i & 4095);
    float4 a = *(const float4*)(x + i);
    float4 b = *(const float4*)(x + i + 4);
    __half2 h0 = __floats2half2_rn(a.x, a.y), h1 = __floats2half2_rn(a.z, a.w);
    __half2 h2 = __floats2half2_rn(b.x, b.y), h3 = __floats2half2_rn(b.z, b.w);
    uint4 o; o.x = *(uint32_t*)&h0; o.y = *(uint32_t*)&h1; o.z = *(uint32_t*)&h2; o.w = *(uint32_t*)&h3;
    int mt = row >> 8, rl = row & 255, c = col >> 6, k = col & 63;
    size_t off = ((size_t)(mt * 64 + c) << 15) + sw128((uint32_t)(rl * 128 + k * 2));
    *(uint4*)((char*)g_xh + off) = o;
}
__global__ void conv_w_tiled(const float* __restrict__ v) {
    size_t i = ((size_t)blockIdx.x * 256 + threadIdx.x) * 8;
    int blk = (int)(i >> 12), w = (int)(i & 4095);
    int o = w >> 6, b = w & 63;
    float4 a = *(const float4*)(v + i);
    float4 bb = *(const float4*)(v + i + 4);
    __half2 h0 = __floats2half2_rn(a.x, a.y), h1 = __floats2half2_rn(a.z, a.w);
    __half2 h2 = __floats2half2_rn(bb.x, bb.y), h3 = __floats2half2_rn(bb.z, bb.w);
    uint4 o4; o4.x = *(uint32_t*)&h0; o4.y = *(uint32_t*)&h1; o4.z = *(uint32_t*)&h2; o4.w = *(uint32_t*)&h3;
    size_t off = ((size_t)blk << 13) + sw128((uint32_t)(o * 128 + b * 2));
    *(uint4*)((char*)g_wt + off) = o4;
}
__global__ void build_sched(const int* __restrict__ cols) {
    int g = threadIdx.x;
    if (g >= 16) return;
    int n = 0;
    for (int c = 0; c < 64; c++)
        for (int rl = 0; rl < 4; rl++)
            for (int j = 0; j < 16; j++)
                if (cols[(g * 4 + rl) * 16 + j] == c)
                    g_ops[g * 64 + n++] = (c << 16) | (rl << 8) | j;
}

// ================= tcgen05 kernel source (NVRTC, sm_103a) =================
// 4 row-blocks per CTA; x ring 5x32KB @0, W ring 6x8KB @163840, barriers @212992.
// Ring slack: x lookahead 3 (ring 5), W refill i+4 (ring 6) -> waits target
// commits >=2 ops old, so the control thread never drains the tensor queue.
static const char* kSRC = R"XX(
typedef unsigned long long ull;
#define WAITB(ad,ph) {unsigned _d; do{ asm volatile("{.reg .pred P; mbarrier.try_wait.parity.acquire.cta.shared::cta.b64 P,[%1],%2; selp.b32 %0,1,0,P;}":"=r"(_d):"r"(ad),"r"(ph):"memory"); }while(!_d);}
#define MMA(d,ad,bd,e) asm volatile("{.reg .pred p; setp.ne.u32 p,%4,0; tcgen05.mma.cta_group::1.kind::f16 [%0],%1,%2,%3,{%5,%5,%5,%5},p;}"::"r"(d),"l"(ad),"l"(bd),"r"(0x8100010u),"r"(e),"r"(0u):"memory")
#define CPB(d,s,n,b) asm volatile("cp.async.bulk.shared::cluster.global.mbarrier::complete_tx::bytes [%0],[%1],%2,[%3];"::"r"(d),"l"(s),"r"(n),"r"(b):"memory")
#define EXPN(a,n) asm volatile("mbarrier.arrive.expect_tx.shared.b64 _,[%0],%1;"::"r"(a),"r"(n):"memory")
#define CMT(a) asm volatile("tcgen05.commit.cta_group::1.mbarrier::arrive::one.shared::cluster.b64 [%0];"::"r"(a):"memory")
#define LDT(rg,ad) asm volatile("tcgen05.ld.sync.aligned.32x32b.x32.b32 {%0,%1,%2,%3,%4,%5,%6,%7,%8,%9,%10,%11,%12,%13,%14,%15,%16,%17,%18,%19,%20,%21,%22,%23,%24,%25,%26,%27,%28,%29,%30,%31},[%32];":"=r"(rg[0]),"=r"(rg[1]),"=r"(rg[2]),"=r"(rg[3]),"=r"(rg[4]),"=r"(rg[5]),"=r"(rg[6]),"=r"(rg[7]),"=r"(rg[8]),"=r"(rg[9]),"=r"(rg[10]),"=r"(rg[11]),"=r"(rg[12]),"=r"(rg[13]),"=r"(rg[14]),"=r"(rg[15]),"=r"(rg[16]),"=r"(rg[17]),"=r"(rg[18]),"=r"(rg[19]),"=r"(rg[20]),"=r"(rg[21]),"=r"(rg[22]),"=r"(rg[23]),"=r"(rg[24]),"=r"(rg[25]),"=r"(rg[26]),"=r"(rg[27]),"=r"(rg[28]),"=r"(rg[29]),"=r"(rg[30]),"=r"(rg[31]):"r"(ad))
#define DESC(a) (0x4000404000010000ULL | (((a) >> 4) & 0x3FFF))
struct __align__(16) F4 { float x,y,z,w; };
extern "C" __global__ void __launch_bounds__(256,1) bsr_tc(
    const unsigned short* xh, const unsigned short* wt, const int* gops,
    const float* bias, float* out)
{
    extern __shared__ char smbuf[];
    unsigned sb; asm("{.reg .u64 t; cvta.to.shared.u64 t,%1; cvt.u32.u64 %0,t;}":"=r"(sb):"l"(smbuf));
    const int tid = threadIdx.x, wid = tid >> 5, lid = tid & 31;
    const int g = blockIdx.x, mt = blockIdx.y;
    const unsigned B = sb + 212992u;
    if (tid == 0)
        for (int i = 0; i < 23; i++)
            asm volatile("mbarrier.init.shared.b64 [%0],1;"::"r"(B+8*i):"memory");
    if (wid == 0) {
        asm volatile("tcgen05.alloc.cta_group::1.sync.aligned.shared::cta.b32 [%0],512;"::"r"(B+184):"memory");
        asm volatile("tcgen05.relinquish_alloc_permit.cta_group::1.sync.aligned;");
    }
    __syncthreads();
    unsigned tmem; asm volatile("ld.shared.b32 %0,[%1];":"=r"(tmem):"r"(B+184));
    if (tid == 0) {
        const char* xg = (const char*)xh + ((ull)mt << 21);
        const char* wg = (const char*)wt + ((ull)g << 19);
        int ops[64];
        for (int i = 0; i < 64; i++) ops[i] = gops[g*64 + i];
        int tl[64]; int ntl = 0; int pc = -1;
        for (int i = 0; i < 64; i++) { int c = ops[i] >> 16; if (c != pc) { tl[ntl++] = c; pc = c; } }
        const unsigned xf = B, xd = B+40, wf = B+80, wd = B+128, ald = B+176;
        // prefill: x tiles 0..2 (lookahead 3), W ops 0..5 (ring 6)
        for (int t = 0; t < 3 && t < ntl; t++) {
            EXPN(xf+8*t, 32768u);
            CPB(sb + 32768u*t, xg + (ull)tl[t]*32768ULL, 32768u, xf+8*t);
        }
        for (int i = 0; i < 6; i++) {
            int rl = (ops[i] >> 8) & 255, j = ops[i] & 255;
            EXPN(wf+8*i, 8192u);
            CPB(sb + 163840u + 8192u*i, wg + (ull)(rl*16 + j)*8192ULL, 8192u, wf+8*i);
        }
        int xi = -1; pc = -1; unsigned fm = 0xFu;
        ull ax = 0;
        for (int i = 0; i < 64; i++) {
            int c = ops[i] >> 16, rl = (ops[i] >> 8) & 255;
            if (c != pc) {
                if (xi >= 0) CMT(xd + 8*(xi % 5));
                pc = c; xi++;
                int tn = xi + 3;                    // prefetch lookahead 3 < ring 5
                if (tn < ntl) {
                    if (tn >= 5) WAITB(xd + 8*(tn % 5), (unsigned)((tn/5 - 1) & 1));
                    EXPN(xf + 8*(tn % 5), 32768u);
                    CPB(sb + 32768u*(tn % 5), xg + (ull)tl[tn]*32768ULL, 32768u, xf + 8*(tn % 5));
                }
                WAITB(xf + 8*(xi % 5), (unsigned)((xi/5) & 1));
                ax = DESC(sb + 32768u*(xi % 5));
            }
            // W refill with slack: op i+4 into slot (i+4)%6, waits wd of op i-2
            int tw = i + 4;
            if (tw < 64 && tw >= 6) {
                WAITB(wd + 8*(tw % 6), (unsigned)((tw/6 - 1) & 1));
                int o2 = ops[tw]; int rl2 = (o2 >> 8) & 255, j2 = o2 & 255;
                EXPN(wf + 8*(tw % 6), 8192u);
                CPB(sb + 163840u + 8192u*(tw % 6), wg + (ull)(rl2*16 + j2)*8192ULL, 8192u, wf + 8*(tw % 6));
            }
            WAITB(wf + 8*(i % 6), (unsigned)((i/6) & 1));
            ull aw = DESC(sb + 163840u + 8192u*(i % 6));
            unsigned e0 = ((fm >> rl) & 1u) ? 0u : 1u;
            fm &= ~(1u << rl);
            unsigned dc = tmem + rl*128;
            for (int k = 0; k < 4; k++) {
                MMA(dc,      ax + 2*k,        aw + 2*k, k ? 1u : e0);
                MMA(dc + 64, ax + 1024 + 2*k, aw + 2*k, k ? 1u : e0);
            }
            CMT(wd + 8*(i % 6));
        }
        CMT(ald);
        WAITB(ald, 0u);
    }
    __syncthreads();
    asm volatile("tcgen05.fence::after_thread_sync;":::"memory");
    int half = wid >> 2, lg = wid & 3;
    int row = mt*256 + half*128 + lg*32 + lid;
    float* po = out + (ull)row*4096 + g*256;
    const float* pb = bias + g*256;
    for (int ch = 0; ch < 8; ch++) {
        int rl = ch >> 1, co = (ch & 1)*32;
        unsigned rg[32];
        LDT(rg, tmem + rl*128 + half*64 + co);
        asm volatile("tcgen05.wait::ld.sync.aligned;":::"memory");
        int cb = rl*64 + co;
        for (int q = 0; q < 32; q += 4) {
            F4 b4 = *(const F4*)(pb + cb + q);
            F4 v;
            v.x = *(float*)&rg[q]   + b4.x; v.y = *(float*)&rg[q+1] + b4.y;
            v.z = *(float*)&rg[q+2] + b4.z; v.w = *(float*)&rg[q+3] + b4.w;
            *(F4*)(po + cb + q) = v;
        }
    }
    __syncthreads();
    if (wid == 0)
        asm volatile("tcgen05.dealloc.cta_group::1.sync.aligned.b32 %0,512;"::"r"(tmem):"memory");
}
)XX";

// ================= NVRTC + driver glue (global ctor = pre-checkpoint) =================
#define JIT_SMEM 213248
struct Jit {
    bool ok = false;
    void* fn = nullptr;
    void* ctx = nullptr;
    void* xp = nullptr;
    void* wp = nullptr;
    void* opsp = nullptr;
    cudaStream_t s2 = nullptr;
    cudaEvent_t evA = nullptr, evB = nullptr;
    int (*Launch)(void*,unsigned,unsigned,unsigned,unsigned,unsigned,unsigned,unsigned,void*,void**,void**) = nullptr;
    int (*CtxSet)(void*) = nullptr;
    Jit() {
        void* hn = dlopen("libnvrtc.so.13", RTLD_NOW);
        if (!hn) hn = dlopen("libnvrtc.so.12", RTLD_NOW);
        if (!hn) hn = dlopen("libnvrtc.so", RTLD_NOW);
        void* hc = dlopen("libcuda.so.1", RTLD_NOW);
        if (!hn || !hc) return;
        auto create  = (int(*)(void**,const char*,const char*,int,const char* const*,const char* const*))dlsym(hn,"nvrtcCreateProgram");
        auto compile = (int(*)(void*,int,const char* const*))dlsym(hn,"nvrtcCompileProgram");
        auto cbsz    = (int(*)(void*,size_t*))dlsym(hn,"nvrtcGetCUBINSize");
        auto cbin    = (int(*)(void*,char*))dlsym(hn,"nvrtcGetCUBIN");
        auto ptxsz   = (int(*)(void*,size_t*))dlsym(hn,"nvrtcGetPTXSize");
        auto ptx     = (int(*)(void*,char*))dlsym(hn,"nvrtcGetPTX");
        auto cuInit_ = (int(*)(unsigned))dlsym(hc,"cuInit");
        auto devGet  = (int(*)(int*,int))dlsym(hc,"cuDeviceGet");
        auto ctxRet  = (int(*)(void**,int))dlsym(hc,"cuDevicePrimaryCtxRetain");
        auto modLoad = (int(*)(void**,const void*))dlsym(hc,"cuModuleLoadData");
        auto modFn   = (int(*)(void**,void*,const char*))dlsym(hc,"cuModuleGetFunction");
        auto fnAttr  = (int(*)(void*,int,int))dlsym(hc,"cuFuncSetAttribute");
        CtxSet = (int(*)(void*))dlsym(hc,"cuCtxSetCurrent");
        Launch = (int(*)(void*,unsigned,unsigned,unsigned,unsigned,unsigned,unsigned,unsigned,void*,void**,void**))dlsym(hc,"cuLaunchKernel");
        if (!create || !compile || !cbsz || !cbin || !ptxsz || !ptx || !cuInit_ || !devGet ||
            !ctxRet || !CtxSet || !modLoad || !modFn || !fnAttr || !Launch) return;

        if (cudaGetSymbolAddress(&xp, g_xh) != cudaSuccess) return;
        if (cudaGetSymbolAddress(&wp, g_wt) != cudaSuccess) return;
        if (cudaGetSymbolAddress(&opsp, g_ops) != cudaSuccess) return;
        if (cudaStreamCreateWithFlags(&s2, cudaStreamNonBlocking) != cudaSuccess) return;
        if (cudaEventCreateWithFlags(&evA, cudaEventDisableTiming) != cudaSuccess) return;
        if (cudaEventCreateWithFlags(&evB, cudaEventDisableTiming) != cudaSuccess) return;

        if (cuInit_(0)) return;
        int dev; if (devGet(&dev, 0)) return;
        if (ctxRet(&ctx, dev)) return;
        if (CtxSet(ctx)) return;
        void* prog;
        if (create(&prog, kSRC, "bsr_tc.cu", 0, nullptr, nullptr)) return;
        const char* opts[] = {"--gpu-architecture=sm_103a"};
        if (compile(prog, 1, opts)) return;
        void* mod = nullptr;
        size_t n = 0;
        if (cbsz(prog, &n) == 0 && n > 0) {
            char* buf = new char[n];
            if (cbin(prog, buf) == 0 && modLoad(&mod, buf) != 0) mod = nullptr;
        }
        if (!mod) {
            if (ptxsz(prog, &n) || n == 0) return;
            char* buf = new char[n];
            if (ptx(prog, buf)) return;
            if (modLoad(&mod, buf)) return;
        }
        if (modFn(&fn, mod, "bsr_tc")) return;
        if (fnAttr(fn, 8 /*MAX_DYNAMIC_SHARED_SIZE_BYTES*/, JIT_SMEM)) return;
        ok = true;
    }
};
static Jit g_jit;

// ================= mma.sync fallback (proven ~242us) =================
__global__ void conv_x_flat(const float* __restrict__ x) {
    size_t i = ((size_t)blockIdx.x * 256 + threadIdx.x) * 8;
    float4 a = *(const float4*)(x + i);
    float4 b = *(const float4*)(x + i + 4);
    __half2 h0 = __floats2half2_rn(a.x, a.y), h1 = __floats2half2_rn(a.z, a.w);
    __half2 h2 = __floats2half2_rn(b.x, b.y), h3 = __floats2half2_rn(b.z, b.w);
    uint4 o; o.x = *(uint32_t*)&h0; o.y = *(uint32_t*)&h1; o.z = *(uint32_t*)&h2; o.w = *(uint32_t*)&h3;
    *(uint4*)(g_xh + i) = o;
}
__global__ void conv_w_flat(const float* __restrict__ v) {
    __shared__ float t[64][65];
    int blk = blockIdx.x, tid = threadIdx.x;
    const float* src = v + (size_t)blk * 4096;
    #pragma unroll
    for (int k = 0; k < 16; k++) t[k * 4 + (tid >> 6)][tid & 63] = src[(k * 4 + (tid >> 6)) * 64 + (tid & 63)];
    __syncthreads();
    __half* dst = g_wt + (size_t)blk * 4096;
    #pragma unroll
    for (int k = 0; k < 16; k++) {
        int b = k * 4 + (tid >> 6), o = tid & 63;
        dst[b * 64 + o] = __float2half(t[o][b]);
    }
}
__device__ __forceinline__ uint32_t smem_u32(const void* p) {
    uint32_t a;
    asm("{ .reg .u64 t; cvta.to.shared.u64 t, %1; cvt.u32.u64 %0, t; }" : "=r"(a) : "l"(p));
    return a;
}
__device__ __forceinline__ void cp16(uint32_t s, const void* g) {
    asm volatile("cp.async.cg.shared.global [%0], [%1], 16;" :: "r"(s), "l"(g));
}
__device__ __forceinline__ void ldsm4(uint32_t* d, uint32_t a) {
    asm volatile("ldmatrix.sync.aligned.m8n8.x4.shared.b16 {%0,%1,%2,%3}, [%4];"
                 : "=r"(d[0]), "=r"(d[1]), "=r"(d[2]), "=r"(d[3]) : "r"(a));
}
__device__ __forceinline__ void ldsm4t(uint32_t* d, uint32_t a) {
    asm volatile("ldmatrix.sync.aligned.m8n8.x4.trans.shared.b16 {%0,%1,%2,%3}, [%4];"
                 : "=r"(d[0]), "=r"(d[1]), "=r"(d[2]), "=r"(d[3]) : "r"(a));
}
__device__ __forceinline__ void mma16816(float* c, const uint32_t* a, const uint32_t* b) {
    asm volatile(
        "mma.sync.aligned.m16n8k16.row.col.f32.f16.f16.f32 "
        "{%0,%1,%2,%3}, {%4,%5,%6,%7}, {%8,%9}, {%0,%1,%2,%3};"
        : "+f"(c[0]), "+f"(c[1]), "+f"(c[2]), "+f"(c[3])
        : "r"(a[0]), "r"(a[1]), "r"(a[2]), "r"(a[3]), "r"(b[0]), "r"(b[1]));
}
#define FB_SMEM 163840
__global__ void __launch_bounds__(256, 1)
bsr_fb(const float* __restrict__ bias, const int* __restrict__ cols, float* __restrict__ out) {
    extern __shared__ char smem[];
    const uint32_t sb = smem_u32(smem);
    const int r = blockIdx.x, mt = blockIdx.y;
    const int tid = threadIdx.x, warp = tid >> 5, lane = tid & 31;
    const int wm = warp >> 1, wn = warp & 1;
    int cidx[BPR];
    #pragma unroll
    for (int j = 0; j < BPR; j++) cidx[j] = __ldg(&cols[r * BPR + j]);
    const __half* xg = g_xh + (size_t)mt * 256 * INF;
    const __half* wg = g_wt + (size_t)r * BPR * BS * BS;
    float acc[4][4][4];
    #pragma unroll
    for (int mi = 0; mi < 4; mi++)
        #pragma unroll
        for (int ni = 0; ni < 4; ni++)
            #pragma unroll
            for (int q = 0; q < 4; q++) acc[mi][ni][q] = 0.0f;
    auto issue = [&](int j) {
        int s = j & 3;
        const char* xsrc = (const char*)(xg + (size_t)cidx[j] * BS);
        uint32_t xs = sb + s * 32768;
        #pragma unroll
        for (int k = 0; k < 8; k++) {
            int q = tid + k * 256, row = q >> 3, ch = q & 7;
            cp16(xs + row * 128 + ((ch ^ (row & 7)) << 4), xsrc + (size_t)row * (INF * 2) + ch * 16);
        }
        const char* wsrc = (const char*)(wg + (size_t)j * BS * BS);
        uint32_t ws = sb + 131072 + s * 8192;
        #pragma unroll
        for (int k = 0; k < 2; k++) {
            int q = tid + k * 256, row = q >> 3, ch = q & 7;
            cp16(ws + row * 128 + ((ch ^ (row & 7)) << 4), wsrc + row * 128 + ch * 16);
        }
        asm volatile("cp.async.commit_group;");
    };
    issue(0); issue(1); issue(2);
    const int mat = lane >> 3, rl = lane & 7;
    for (int j = 0; j < BPR; j++) {
        int rem = (BPR - 1) - j;
        if (rem >= 2)      asm volatile("cp.async.wait_group 2;");
        else if (rem == 1) asm volatile("cp.async.wait_group 1;");
        else               asm volatile("cp.async.wait_group 0;");
        __syncthreads();
        uint32_t xs = sb + (j & 3) * 32768;
        uint32_t ws = sb + 131072 + (j & 3) * 8192;
        #pragma unroll
        for (int ks = 0; ks < 4; ks++) {
            uint32_t a[4][4], b[4][2];
            #pragma unroll
            for (int mi = 0; mi < 4; mi++) {
                int row = wm * 64 + mi * 16 + (mat & 1) * 8 + rl;
                int ch = 2 * ks + (mat >> 1);
                ldsm4(a[mi], xs + row * 128 + ((ch ^ (row & 7)) << 4));
            }
            #pragma unroll
            for (int nh = 0; nh < 2; nh++) {
                int krow = ks * 16 + (mat & 1) * 8 + rl;
                int nch = wn * 4 + nh * 2 + (mat >> 1);
                uint32_t t[4];
                ldsm4t(t, ws + krow * 128 + ((nch ^ (krow & 7)) << 4));
                b[nh * 2][0] = t[0]; b[nh * 2][1] = t[1];
                b[nh * 2 + 1][0] = t[2]; b[nh * 2 + 1][1] = t[3];
            }
            #pragma unroll
            for (int mi = 0; mi < 4; mi++)
                #pragma unroll
                for (int ni = 0; ni < 4; ni++)
                    mma16816(acc[mi][ni], a[mi], b[ni]);
        }
        if (j + 3 < BPR) issue(j + 3);
    }
    #pragma unroll
    for (int mi = 0; mi < 4; mi++)
        #pragma unroll
        for (int ni = 0; ni < 4; ni++) {
            int rr = mt * 256 + wm * 64 + mi * 16 + (lane >> 2);
            int cc = r * BS + wn * 32 + ni * 8 + 2 * (lane & 3);
            float2 bv = *(const float2*)(bias + cc);
            float2 v0 = {acc[mi][ni][0] + bv.x, acc[mi][ni][1] + bv.y};
            float2 v1 = {acc[mi][ni][2] + bv.x, acc[mi][ni][3] + bv.y};
            *(float2*)(out + (size_t)rr * OUTF + cc) = v0;
            *(float2*)(out + (size_t)(rr + 8) * OUTF + cc) = v1;
        }
}

// ================= launch =================
extern "C" void kernel_launch(void* const* d_in, const int* in_sizes, int n_in,
                              void* d_out, int out_size) {
    const float* x      = (const float*)d_in[0];
    const float* values = (const float*)d_in[1];
    const float* bias   = (const float*)d_in[2];
    const int*   cols   = (const int*)d_in[3];
    float* out = (float*)d_out;

    if (g_jit.ok) {
        // conv_w + sched on side stream, conv_x on main -> overlap
        conv_w_tiled<<<2048, 256, 0, g_jit.s2>>>(values);
        build_sched<<<1, 16, 0, g_jit.s2>>>(cols);
        conv_x_tiled<<<16384, 256>>>(x);
        cudaEventRecord(g_jit.evA, 0);
        cudaStreamWaitEvent(g_jit.s2, g_jit.evA, 0);
        g_jit.CtxSet(g_jit.ctx);
        void* args[] = {&g_jit.xp, &g_jit.wp, &g_jit.opsp, (void*)&bias, (void*)&out};
        g_jit.Launch(g_jit.fn, 16, 32, 1, 256, 1, 1, JIT_SMEM, (void*)g_jit.s2, args, nullptr);
        cudaEventRecord(g_jit.evB, g_jit.s2);
        cudaStreamWaitEvent(0, g_jit.evB, 0);
    } else {
        conv_x_flat<<<(BATCH * (size_t)INF / 8) / 256, 256>>>(x);
        conv_w_flat<<<NBR * BPR, 256>>>(values);
        cudaFuncSetAttribute(bsr_fb, cudaFuncAttributeMaxDynamicSharedMemorySize, FB_SMEM);
        bsr_fb<<<dim3(NBR, 32), 256, FB_SMEM>>>(bias, cols, out);
    }
}

// round 15
// speedup vs baseline: 2.5509x; 2.1558x over previous
#include <cuda_runtime.h>
#include <cuda_fp16.h>
#include <cstdint>
#include <cstring>
#include <dlfcn.h>

#define BATCH 8192
#define INF   4096
#define OUTF  4096
#define BS    64
#define NBR   64
#define BPR   16
#define NCHUNK 8

// ================= shared scratch (allocation-free) =================
__device__ __half g_xh[(size_t)BATCH * INF];          // 64MB
__device__ __half g_wt[(size_t)NBR * BPR * BS * BS];  // 8MB

__host__ __device__ __forceinline__ uint32_t sw128(uint32_t b) {
    return b ^ ((b >> 3) & 0x70);
}

// ================= prepasses: SW128-swizzled tiles =================
// x tile (mt,c): 256 rows x 64 fp16 (128B rows) at offset (mt*64+c)*32768
// chunked: chunk covers mt in [4*chunk, 4*chunk+4)
__global__ void conv_x_tiled(const float* __restrict__ x, int chunk) {
    size_t base = (size_t)chunk * (BATCH / NCHUNK) * INF;       // elements
    size_t i = base + ((size_t)blockIdx.x * 256 + threadIdx.x) * 8;
    int row = (int)(i >> 12), col = (int)(i & 4095);
    float4 a = *(const float4*)(x + i);
    float4 b = *(const float4*)(x + i + 4);
    __half2 h0 = __floats2half2_rn(a.x, a.y), h1 = __floats2half2_rn(a.z, a.w);
    __half2 h2 = __floats2half2_rn(b.x, b.y), h3 = __floats2half2_rn(b.z, b.w);
    uint4 o; o.x = *(uint32_t*)&h0; o.y = *(uint32_t*)&h1; o.z = *(uint32_t*)&h2; o.w = *(uint32_t*)&h3;
    int mt = row >> 8, rl = row & 255, c = col >> 6, k = col & 63;
    size_t off = ((size_t)(mt * 64 + c) << 15) + sw128((uint32_t)(rl * 128 + k * 2));
    *(uint4*)((char*)g_xh + off) = o;
}
// W block blk=(r*16+j): 64 o-rows x 64 b fp16 at blk*8192 (B operand [N][K])
__global__ void conv_w_tiled(const float* __restrict__ v) {
    size_t i = ((size_t)blockIdx.x * 256 + threadIdx.x) * 8;
    int blk = (int)(i >> 12), w = (int)(i & 4095);
    int o = w >> 6, b = w & 63;
    float4 a = *(const float4*)(v + i);
    float4 bb = *(const float4*)(v + i + 4);
    __half2 h0 = __floats2half2_rn(a.x, a.y), h1 = __floats2half2_rn(a.z, a.w);
    __half2 h2 = __floats2half2_rn(bb.x, bb.y), h3 = __floats2half2_rn(bb.z, bb.w);
    uint4 o4; o4.x = *(uint32_t*)&h0; o4.y = *(uint32_t*)&h1; o4.z = *(uint32_t*)&h2; o4.w = *(uint32_t*)&h3;
    size_t off = ((size_t)blk << 13) + sw128((uint32_t)(o * 128 + b * 2));
    *(uint4*)((char*)g_wt + off) = o4;
}

// ================= tcgen05 kernel source (NVRTC, sm_103a) =================
// EXACT R12 kernel (proven 128us main) + mt_base chunk offset.
static const char* kSRC = R"XX(
#define WAITB(ad,ph) {unsigned _d; do{ asm volatile("{.reg .pred P; mbarrier.try_wait.parity.acquire.cta.shared::cta.b64 P,[%1],%2; selp.b32 %0,1,0,P;}":"=r"(_d):"r"(ad),"r"(ph):"memory"); }while(!_d);}
#define MMA(d,ad,bd,e) asm volatile("{.reg .pred p; setp.ne.u32 p,%4,0; tcgen05.mma.cta_group::1.kind::f16 [%0],%1,%2,%3,{%5,%5,%5,%5},p;}"::"r"(d),"l"(ad),"l"(bd),"r"(0x8100010u),"r"(e),"r"(0u):"memory")
#define CPB(d,s,n,b) asm volatile("cp.async.bulk.shared::cluster.global.mbarrier::complete_tx::bytes [%0],[%1],%2,[%3];"::"r"(d),"l"(s),"r"(n),"r"(b):"memory")
#define EXP(a) asm volatile("mbarrier.arrive.expect_tx.shared.b64 _,[%0],40960;"::"r"(a):"memory")
#define LDT(rg,ad) asm volatile("tcgen05.ld.sync.aligned.32x32b.x32.b32 {%0,%1,%2,%3,%4,%5,%6,%7,%8,%9,%10,%11,%12,%13,%14,%15,%16,%17,%18,%19,%20,%21,%22,%23,%24,%25,%26,%27,%28,%29,%30,%31},[%32];":"=r"(rg[0]),"=r"(rg[1]),"=r"(rg[2]),"=r"(rg[3]),"=r"(rg[4]),"=r"(rg[5]),"=r"(rg[6]),"=r"(rg[7]),"=r"(rg[8]),"=r"(rg[9]),"=r"(rg[10]),"=r"(rg[11]),"=r"(rg[12]),"=r"(rg[13]),"=r"(rg[14]),"=r"(rg[15]),"=r"(rg[16]),"=r"(rg[17]),"=r"(rg[18]),"=r"(rg[19]),"=r"(rg[20]),"=r"(rg[21]),"=r"(rg[22]),"=r"(rg[23]),"=r"(rg[24]),"=r"(rg[25]),"=r"(rg[26]),"=r"(rg[27]),"=r"(rg[28]),"=r"(rg[29]),"=r"(rg[30]),"=r"(rg[31]):"r"(ad))
struct __align__(16) F4 { float x,y,z,w; };
extern "C" __global__ void __launch_bounds__(256,1) bsr_tc(
    const unsigned short* xh, const unsigned short* wt,
    const int* cols, const float* bias, float* out, int mt_base)
{
    extern __shared__ char smbuf[];
    unsigned sb; asm("{.reg .u64 t; cvta.to.shared.u64 t,%1; cvt.u32.u64 %0,t;}":"=r"(sb):"l"(smbuf));
    const int tid = threadIdx.x, wid = tid >> 5, lid = tid & 31;
    const int r = blockIdx.x, mt = blockIdx.y + mt_base;
    if (tid == 0)
        for (int i = 0; i < 4; i++)
            asm volatile("mbarrier.init.shared.b64 [%0],1;"::"r"(sb+81920+8*i):"memory");
    if (wid == 0) {
        asm volatile("tcgen05.alloc.cta_group::1.sync.aligned.shared::cta.b32 [%0],128;"::"r"(sb+81952):"memory");
        asm volatile("tcgen05.relinquish_alloc_permit.cta_group::1.sync.aligned;");
    }
    __syncthreads();
    unsigned tmem; asm volatile("ld.shared.b32 %0,[%1];":"=r"(tmem):"r"(sb+81952));
    if (tid == 0) {
        const char* xg = (const char*)xh + ((unsigned long long)(mt*64) << 15);
        const char* wg = (const char*)wt + ((unsigned long long)r << 17);
        const int* cp = cols + r*16;
        unsigned xs[2] = {sb, sb+32768}, ws[2] = {sb+65536, sb+73728};
        unsigned full[2] = {sb+81920, sb+81928}, done[2] = {sb+81936, sb+81944};
        for (int j = 0; j < 2; j++) {
            EXP(full[j]);
            CPB(xs[j], xg + (unsigned long long)cp[j]*32768ULL, 32768u, full[j]);
            CPB(ws[j], wg + (unsigned long long)j*8192ULL, 8192u, full[j]);
        }
        for (int j = 0; j < 16; j++) {
            int s = j & 1; unsigned ph = (j >> 1) & 1;
            WAITB(full[s], ph);
            unsigned long long ax = 0x4000404000010000ULL | ((xs[s] >> 4) & 0x3FFF);
            unsigned long long aw = 0x4000404000010000ULL | ((ws[s] >> 4) & 0x3FFF);
            for (int k = 0; k < 4; k++) {
                unsigned e = (k | j) ? 1u : 0u;
                MMA(tmem,      ax + 2*k,        aw + 2*k, e);
                MMA(tmem + 64, ax + 1024 + 2*k, aw + 2*k, e);
            }
            asm volatile("tcgen05.commit.cta_group::1.mbarrier::arrive::one.shared::cluster.b64 [%0];"::"r"(done[s]):"memory");
            if (j + 2 < 16) {
                WAITB(done[s], ph);
                EXP(full[s]);
                CPB(xs[s], xg + (unsigned long long)cp[j+2]*32768ULL, 32768u, full[s]);
                CPB(ws[s], wg + (unsigned long long)(j+2)*8192ULL, 8192u, full[s]);
            }
        }
        WAITB(done[0], 1u);
        WAITB(done[1], 1u);
    }
    __syncthreads();
    asm volatile("tcgen05.fence::after_thread_sync;":::"memory");
    unsigned rg[64];
    unsigned ta = tmem + ((wid >> 2) << 6);
    LDT(rg, ta);
    LDT((rg+32), (ta+32));
    asm volatile("tcgen05.wait::ld.sync.aligned;":::"memory");
    int row = mt*256 + ((wid >> 2) << 7) + ((wid & 3) << 5) + lid;
    float* op = out + (unsigned long long)row*4096 + r*64;
    const float* bp = bias + r*64;
    for (int q = 0; q < 64; q += 4) {
        F4 b4 = *(const F4*)(bp + q);
        F4 v;
        v.x = *(float*)&rg[q]   + b4.x; v.y = *(float*)&rg[q+1] + b4.y;
        v.z = *(float*)&rg[q+2] + b4.z; v.w = *(float*)&rg[q+3] + b4.w;
        *(F4*)(op + q) = v;
    }
    __syncthreads();
    if (wid == 0)
        asm volatile("tcgen05.dealloc.cta_group::1.sync.aligned.b32 %0,128;"::"r"(tmem):"memory");
}
)XX";

// ================= NVRTC + driver glue (global ctor = pre-checkpoint) =================
#define JIT_SMEM 82176
struct Jit {
    bool ok = false;
    void* fn = nullptr;
    void* ctx = nullptr;
    void* xp = nullptr;
    void* wp = nullptr;
    cudaStream_t sx = nullptr;
    cudaStream_t sm[NCHUNK] = {};
    cudaEvent_t root = nullptr, evW = nullptr;
    cudaEvent_t evx[NCHUNK] = {}, evm[NCHUNK] = {};
    int (*Launch)(void*,unsigned,unsigned,unsigned,unsigned,unsigned,unsigned,unsigned,void*,void**,void**) = nullptr;
    int (*CtxSet)(void*) = nullptr;
    Jit() {
        void* hn = dlopen("libnvrtc.so.13", RTLD_NOW);
        if (!hn) hn = dlopen("libnvrtc.so.12", RTLD_NOW);
        if (!hn) hn = dlopen("libnvrtc.so", RTLD_NOW);
        void* hc = dlopen("libcuda.so.1", RTLD_NOW);
        if (!hn || !hc) return;
        auto create  = (int(*)(void**,const char*,const char*,int,const char* const*,const char* const*))dlsym(hn,"nvrtcCreateProgram");
        auto compile = (int(*)(void*,int,const char* const*))dlsym(hn,"nvrtcCompileProgram");
        auto cbsz    = (int(*)(void*,size_t*))dlsym(hn,"nvrtcGetCUBINSize");
        auto cbin    = (int(*)(void*,char*))dlsym(hn,"nvrtcGetCUBIN");
        auto ptxsz   = (int(*)(void*,size_t*))dlsym(hn,"nvrtcGetPTXSize");
        auto ptx     = (int(*)(void*,char*))dlsym(hn,"nvrtcGetPTX");
        auto cuInit_ = (int(*)(unsigned))dlsym(hc,"cuInit");
        auto devGet  = (int(*)(int*,int))dlsym(hc,"cuDeviceGet");
        auto ctxRet  = (int(*)(void**,int))dlsym(hc,"cuDevicePrimaryCtxRetain");
        auto modLoad = (int(*)(void**,const void*))dlsym(hc,"cuModuleLoadData");
        auto modFn   = (int(*)(void**,void*,const char*))dlsym(hc,"cuModuleGetFunction");
        auto fnAttr  = (int(*)(void*,int,int))dlsym(hc,"cuFuncSetAttribute");
        CtxSet = (int(*)(void*))dlsym(hc,"cuCtxSetCurrent");
        Launch = (int(*)(void*,unsigned,unsigned,unsigned,unsigned,unsigned,unsigned,unsigned,void*,void**,void**))dlsym(hc,"cuLaunchKernel");
        if (!create || !compile || !cbsz || !cbin || !ptxsz || !ptx || !cuInit_ || !devGet ||
            !ctxRet || !CtxSet || !modLoad || !modFn || !fnAttr || !Launch) return;

        if (cudaGetSymbolAddress(&xp, g_xh) != cudaSuccess) return;
        if (cudaGetSymbolAddress(&wp, g_wt) != cudaSuccess) return;
        if (cudaStreamCreateWithFlags(&sx, cudaStreamNonBlocking) != cudaSuccess) return;
        for (int i = 0; i < NCHUNK; i++)
            if (cudaStreamCreateWithFlags(&sm[i], cudaStreamNonBlocking) != cudaSuccess) return;
        if (cudaEventCreateWithFlags(&root, cudaEventDisableTiming) != cudaSuccess) return;
        if (cudaEventCreateWithFlags(&evW, cudaEventDisableTiming) != cudaSuccess) return;
        for (int i = 0; i < NCHUNK; i++) {
            if (cudaEventCreateWithFlags(&evx[i], cudaEventDisableTiming) != cudaSuccess) return;
            if (cudaEventCreateWithFlags(&evm[i], cudaEventDisableTiming) != cudaSuccess) return;
        }

        if (cuInit_(0)) return;
        int dev; if (devGet(&dev, 0)) return;
        if (ctxRet(&ctx, dev)) return;
        if (CtxSet(ctx)) return;
        void* prog;
        if (create(&prog, kSRC, "bsr_tc.cu", 0, nullptr, nullptr)) return;
        const char* opts[] = {"--gpu-architecture=sm_103a"};
        if (compile(prog, 1, opts)) return;
        void* mod = nullptr;
        size_t n = 0;
        if (cbsz(prog, &n) == 0 && n > 0) {
            char* buf = new char[n];
            if (cbin(prog, buf) == 0 && modLoad(&mod, buf) != 0) mod = nullptr;
        }
        if (!mod) {
            if (ptxsz(prog, &n) || n == 0) return;
            char* buf = new char[n];
            if (ptx(prog, buf)) return;
            if (modLoad(&mod, buf)) return;
        }
        if (modFn(&fn, mod, "bsr_tc")) return;
        if (fnAttr(fn, 8 /*MAX_DYNAMIC_SHARED_SIZE_BYTES*/, JIT_SMEM)) return;
        ok = true;
    }
};
static Jit g_jit;

// ================= mma.sync fallback (proven ~242us) =================
__global__ void conv_x_flat(const float* __restrict__ x) {
    size_t i = ((size_t)blockIdx.x * 256 + threadIdx.x) * 8;
    float4 a = *(const float4*)(x + i);
    float4 b = *(const float4*)(x + i + 4);
    __half2 h0 = __floats2half2_rn(a.x, a.y), h1 = __floats2half2_rn(a.z, a.w);
    __half2 h2 = __floats2half2_rn(b.x, b.y), h3 = __floats2half2_rn(b.z, b.w);
    uint4 o; o.x = *(uint32_t*)&h0; o.y = *(uint32_t*)&h1; o.z = *(uint32_t*)&h2; o.w = *(uint32_t*)&h3;
    *(uint4*)(g_xh + i) = o;
}
__global__ void conv_w_flat(const float* __restrict__ v) {
    __shared__ float t[64][65];
    int blk = blockIdx.x, tid = threadIdx.x;
    const float* src = v + (size_t)blk * 4096;
    #pragma unroll
    for (int k = 0; k < 16; k++) t[k * 4 + (tid >> 6)][tid & 63] = src[(k * 4 + (tid >> 6)) * 64 + (tid & 63)];
    __syncthreads();
    __half* dst = g_wt + (size_t)blk * 4096;
    #pragma unroll
    for (int k = 0; k < 16; k++) {
        int b = k * 4 + (tid >> 6), o = tid & 63;
        dst[b * 64 + o] = __float2half(t[o][b]);
    }
}
__device__ __forceinline__ uint32_t smem_u32(const void* p) {
    uint32_t a;
    asm("{ .reg .u64 t; cvta.to.shared.u64 t, %1; cvt.u32.u64 %0, t; }" : "=r"(a) : "l"(p));
    return a;
}
__device__ __forceinline__ void cp16(uint32_t s, const void* g) {
    asm volatile("cp.async.cg.shared.global [%0], [%1], 16;" :: "r"(s), "l"(g));
}
__device__ __forceinline__ void ldsm4(uint32_t* d, uint32_t a) {
    asm volatile("ldmatrix.sync.aligned.m8n8.x4.shared.b16 {%0,%1,%2,%3}, [%4];"
                 : "=r"(d[0]), "=r"(d[1]), "=r"(d[2]), "=r"(d[3]) : "r"(a));
}
__device__ __forceinline__ void ldsm4t(uint32_t* d, uint32_t a) {
    asm volatile("ldmatrix.sync.aligned.m8n8.x4.trans.shared.b16 {%0,%1,%2,%3}, [%4];"
                 : "=r"(d[0]), "=r"(d[1]), "=r"(d[2]), "=r"(d[3]) : "r"(a));
}
__device__ __forceinline__ void mma16816(float* c, const uint32_t* a, const uint32_t* b) {
    asm volatile(
        "mma.sync.aligned.m16n8k16.row.col.f32.f16.f16.f32 "
        "{%0,%1,%2,%3}, {%4,%5,%6,%7}, {%8,%9}, {%0,%1,%2,%3};"
        : "+f"(c[0]), "+f"(c[1]), "+f"(c[2]), "+f"(c[3])
        : "r"(a[0]), "r"(a[1]), "r"(a[2]), "r"(a[3]), "r"(b[0]), "r"(b[1]));
}
#define FB_SMEM 163840
__global__ void __launch_bounds__(256, 1)
bsr_fb(const float* __restrict__ bias, const int* __restrict__ cols, float* __restrict__ out) {
    extern __shared__ char smem[];
    const uint32_t sb = smem_u32(smem);
    const int r = blockIdx.x, mt = blockIdx.y;
    const int tid = threadIdx.x, warp = tid >> 5, lane = tid & 31;
    const int wm = warp >> 1, wn = warp & 1;
    int cidx[BPR];
    #pragma unroll
    for (int j = 0; j < BPR; j++) cidx[j] = __ldg(&cols[r * BPR + j]);
    const __half* xg = g_xh + (size_t)mt * 256 * INF;
    const __half* wg = g_wt + (size_t)r * BPR * BS * BS;
    float acc[4][4][4];
    #pragma unroll
    for (int mi = 0; mi < 4; mi++)
        #pragma unroll
        for (int ni = 0; ni < 4; ni++)
            #pragma unroll
            for (int q = 0; q < 4; q++) acc[mi][ni][q] = 0.0f;
    auto issue = [&](int j) {
        int s = j & 3;
        const char* xsrc = (const char*)(xg + (size_t)cidx[j] * BS);
        uint32_t xs = sb + s * 32768;
        #pragma unroll
        for (int k = 0; k < 8; k++) {
            int q = tid + k * 256, row = q >> 3, ch = q & 7;
            cp16(xs + row * 128 + ((ch ^ (row & 7)) << 4), xsrc + (size_t)row * (INF * 2) + ch * 16);
        }
        const char* wsrc = (const char*)(wg + (size_t)j * BS * BS);
        uint32_t ws = sb + 131072 + s * 8192;
        #pragma unroll
        for (int k = 0; k < 2; k++) {
            int q = tid + k * 256, row = q >> 3, ch = q & 7;
            cp16(ws + row * 128 + ((ch ^ (row & 7)) << 4), wsrc + row * 128 + ch * 16);
        }
        asm volatile("cp.async.commit_group;");
    };
    issue(0); issue(1); issue(2);
    const int mat = lane >> 3, rl = lane & 7;
    for (int j = 0; j < BPR; j++) {
        int rem = (BPR - 1) - j;
        if (rem >= 2)      asm volatile("cp.async.wait_group 2;");
        else if (rem == 1) asm volatile("cp.async.wait_group 1;");
        else               asm volatile("cp.async.wait_group 0;");
        __syncthreads();
        uint32_t xs = sb + (j & 3) * 32768;
        uint32_t ws = sb + 131072 + (j & 3) * 8192;
        #pragma unroll
        for (int ks = 0; ks < 4; ks++) {
            uint32_t a[4][4], b[4][2];
            #pragma unroll
            for (int mi = 0; mi < 4; mi++) {
                int row = wm * 64 + mi * 16 + (mat & 1) * 8 + rl;
                int ch = 2 * ks + (mat >> 1);
                ldsm4(a[mi], xs + row * 128 + ((ch ^ (row & 7)) << 4));
            }
            #pragma unroll
            for (int nh = 0; nh < 2; nh++) {
                int krow = ks * 16 + (mat & 1) * 8 + rl;
                int nch = wn * 4 + nh * 2 + (mat >> 1);
                uint32_t t[4];
                ldsm4t(t, ws + krow * 128 + ((nch ^ (krow & 7)) << 4));
                b[nh * 2][0] = t[0]; b[nh * 2][1] = t[1];
                b[nh * 2 + 1][0] = t[2]; b[nh * 2 + 1][1] = t[3];
            }
            #pragma unroll
            for (int mi = 0; mi < 4; mi++)
                #pragma unroll
                for (int ni = 0; ni < 4; ni++)
                    mma16816(acc[mi][ni], a[mi], b[ni]);
        }
        if (j + 3 < BPR) issue(j + 3);
    }
    #pragma unroll
    for (int mi = 0; mi < 4; mi++)
        #pragma unroll
        for (int ni = 0; ni < 4; ni++) {
            int rr = mt * 256 + wm * 64 + mi * 16 + (lane >> 2);
            int cc = r * BS + wn * 32 + ni * 8 + 2 * (lane & 3);
            float2 bv = *(const float2*)(bias + cc);
            float2 v0 = {acc[mi][ni][0] + bv.x, acc[mi][ni][1] + bv.y};
            float2 v1 = {acc[mi][ni][2] + bv.x, acc[mi][ni][3] + bv.y};
            *(float2*)(out + (size_t)rr * OUTF + cc) = v0;
            *(float2*)(out + (size_t)(rr + 8) * OUTF + cc) = v1;
        }
}

// ================= launch =================
extern "C" void kernel_launch(void* const* d_in, const int* in_sizes, int n_in,
                              void* d_out, int out_size) {
    const float* x      = (const float*)d_in[0];
    const float* values = (const float*)d_in[1];
    const float* bias   = (const float*)d_in[2];
    const int*   cols   = (const int*)d_in[3];
    float* out = (float*)d_out;

    if (g_jit.ok) {
        // Fork: conv_x chunks on side stream; conv_w on stream 0.
        cudaEventRecord(g_jit.root, 0);
        cudaStreamWaitEvent(g_jit.sx, g_jit.root, 0);
        for (int c = 0; c < NCHUNK; c++) {
            conv_x_tiled<<<2048, 256, 0, g_jit.sx>>>(x, c);
            cudaEventRecord(g_jit.evx[c], g_jit.sx);
        }
        conv_w_tiled<<<2048, 256>>>(values);
        cudaEventRecord(g_jit.evW, 0);

        g_jit.CtxSet(g_jit.ctx);
        int mtb[NCHUNK];
        for (int c = 0; c < NCHUNK; c++) {
            mtb[c] = c * (32 / NCHUNK);
            cudaStreamWaitEvent(g_jit.sm[c], g_jit.evx[c], 0);
            cudaStreamWaitEvent(g_jit.sm[c], g_jit.evW, 0);
            void* args[] = {&g_jit.xp, &g_jit.wp, (void*)&cols, (void*)&bias, (void*)&out, &mtb[c]};
            g_jit.Launch(g_jit.fn, NBR, 32 / NCHUNK, 1, 256, 1, 1, JIT_SMEM,
                         (void*)g_jit.sm[c], args, nullptr);
            cudaEventRecord(g_jit.evm[c], g_jit.sm[c]);
        }
        for (int c = 0; c < NCHUNK; c++)
            cudaStreamWaitEvent(0, g_jit.evm[c], 0);
    } else {
        conv_x_flat<<<(BATCH * (size_t)INF / 8) / 256, 256>>>(x);
        conv_w_flat<<<NBR * BPR, 256>>>(values);
        cudaFuncSetAttribute(bsr_fb, cudaFuncAttributeMaxDynamicSharedMemorySize, FB_SMEM);
        bsr_fb<<<dim3(NBR, 32), 256, FB_SMEM>>>(bias, cols, out);
    }
}